// round 4
// baseline (speedup 1.0000x reference)
#include <cuda_runtime.h>
#include <cuda_bf16.h>
#include <math.h>

// Problem constants
#define NN 4096
#define HH 128
#define EE 131072

// ---------------- scratch (static device arrays; no allocation) ----------------
__device__ float g_h1[NN * HH];
__device__ float g_h2[NN * HH];
__device__ float g_z1[NN * HH];
__device__ float g_z3[NN * HH];
__device__ float g_qkv[2 * NN * 3 * HH];
__device__ float g_obar[NN * HH];
__device__ float g_h1mix[NN * HH];
__device__ float g_ToM[HH * HH];
__device__ float g_ToF[HH * HH];
__device__ float g_part[4 * NN * HH];                 // split-K partials
__device__ __nv_bfloat16 g_G1h[NN * NN];              // pre-split G1 hi
__device__ __nv_bfloat16 g_G1l[NN * NN];              // pre-split G1 lo
__device__ __nv_bfloat16 g_G3h[NN * NN];
__device__ __nv_bfloat16 g_G3l[NN * NN];
__device__ __nv_bfloat16 g_BtYh[HH * NN];             // Y^T hi  [Nc=128][K=4096]
__device__ __nv_bfloat16 g_BtYl[HH * NN];
__device__ __nv_bfloat16 g_BtWh[3 * HH * HH];         // weight Bt hi (max 384x128)
__device__ __nv_bfloat16 g_BtWl[3 * HH * HH];
__device__ __nv_bfloat16 g_mixh[2 * NN * HH];         // MHA-mix input hi/lo
__device__ __nv_bfloat16 g_mixl[2 * NN * HH];
__device__ __nv_bfloat16 g_fush[2 * NN * HH];         // MHA-fus input hi/lo
__device__ __nv_bfloat16 g_fusl[2 * NN * HH];

// ---------------- helpers -------------------------------------------------------
__device__ __forceinline__ void split_bf16(float v, __nv_bfloat16& h, __nv_bfloat16& l)
{
    h = __float2bfloat16(v);
    l = __float2bfloat16(v - __bfloat162float(h));
}

__device__ __forceinline__ void cp16(void* dst, const void* src)
{
    unsigned int d = (unsigned int)__cvta_generic_to_shared(dst);
    asm volatile("cp.async.cg.shared.global [%0], [%1], 16;\n" :: "r"(d), "l"(src));
}

#define MMA_BF16(d, a0, a1, a2, a3, b0, b1)                                   \
    asm volatile(                                                             \
        "mma.sync.aligned.m16n8k16.row.col.f32.bf16.bf16.f32 "                \
        "{%0,%1,%2,%3}, {%4,%5,%6,%7}, {%8,%9}, {%0,%1,%2,%3};"               \
        : "+f"(d[0]), "+f"(d[1]), "+f"(d[2]), "+f"(d[3])                      \
        : "r"(a0), "r"(a1), "r"(a2), "r"(a3), "r"(b0), "r"(b1))

// =======================================================================
// Tensor-core GEMM: C[M,Nc] = A[M,K] @ B[K,Nc]
//   A pre-split bf16 hi/lo row-major [M][K]; B pre-split transposed [Nc][K].
//   Emulated fp32: Ah*Bh + Ah*Bl + Al*Bh (fp32 accumulate).
//   grid (M/128, Nc/128, KS). KS>1 -> partials at C + z*M*Nc (no bias).
//   Dynamic smem: 2 stages x 4 arrays x 128x40 bf16 = 81920 B.
// =======================================================================
#define TGEMM_SMEM (2 * 4 * 128 * 40 * 2)

__global__ __launch_bounds__(256) void tgemm_kernel(
    const __nv_bfloat16* __restrict__ Ah, const __nv_bfloat16* __restrict__ Al,
    const __nv_bfloat16* __restrict__ Bh, const __nv_bfloat16* __restrict__ Bl,
    float* __restrict__ C, int M, int K, int Nc,
    const float* __restrict__ bias)
{
    extern __shared__ __nv_bfloat16 smem[];
    const int ST = 128 * 40;   // elems per array

    const int tid  = threadIdx.x;
    const int row0 = blockIdx.x * 128;
    const int col0 = blockIdx.y * 128;
    const int KS     = gridDim.z;
    const int kiters = K / (32 * KS);
    const int kbase  = blockIdx.z * kiters * 32;

    const int warp = tid >> 5, lane = tid & 31;
    const int wm = warp & 3, wn = warp >> 2;          // 4 x 2 warp grid
    const int grp = lane >> 2, thr4 = lane & 3;

    float acc[2][8][4];
#pragma unroll
    for (int mf = 0; mf < 2; mf++)
#pragma unroll
        for (int nf = 0; nf < 8; nf++)
#pragma unroll
            for (int i = 0; i < 4; i++) acc[mf][nf][i] = 0.0f;

    // loader precomputes
    const int l_r  = tid >> 1;               // 0..127  (2 threads per row, 16B each)
    const int l_c8 = (tid & 1) * 16;         // 0 or 16 (bf16 units; 16 elems = 32B)
    // each thread moves 32B per array per stage as 2x16B
#define LOAD_STAGE(it, buf)                                                        \
    {                                                                              \
        const int kt = kbase + (it) * 32;                                          \
        __nv_bfloat16* s0 = smem + (buf) * 4 * ST;                                 \
        const size_t ga = (size_t)(row0 + l_r) * K + kt + l_c8;                    \
        const size_t gb = (size_t)(col0 + l_r) * K + kt + l_c8;                    \
        __nv_bfloat16* sa = s0 + l_r * 40 + l_c8;                                  \
        cp16(sa,            Ah + ga);                                              \
        cp16(sa + 8,        Ah + ga + 8);                                          \
        cp16(sa + ST,       Al + ga);                                              \
        cp16(sa + ST + 8,   Al + ga + 8);                                          \
        __nv_bfloat16* sb = s0 + 2 * ST + l_r * 40 + l_c8;                         \
        cp16(sb,            Bh + gb);                                              \
        cp16(sb + 8,        Bh + gb + 8);                                          \
        cp16(sb + ST,       Bl + gb);                                              \
        cp16(sb + ST + 8,   Bl + gb + 8);                                          \
        asm volatile("cp.async.commit_group;\n");                                  \
    }

    LOAD_STAGE(0, 0);

    for (int it = 0; it < kiters; it++) {
        if (it + 1 < kiters) {
            LOAD_STAGE(it + 1, (it + 1) & 1);
            asm volatile("cp.async.wait_group 1;\n");
        } else {
            asm volatile("cp.async.wait_group 0;\n");
        }
        __syncthreads();

        const __nv_bfloat16* s0  = smem + (it & 1) * 4 * ST;
        const __nv_bfloat16* pAh = s0;
        const __nv_bfloat16* pAl = s0 + ST;
        const __nv_bfloat16* pBh = s0 + 2 * ST;
        const __nv_bfloat16* pBl = s0 + 3 * ST;

#pragma unroll
        for (int koff = 0; koff < 32; koff += 16) {
            const int c0 = koff + thr4 * 2;
            unsigned int ah[2][4], al[2][4];
#pragma unroll
            for (int mf = 0; mf < 2; mf++) {
                const int mb = wm * 32 + mf * 16;
                ah[mf][0] = *(const unsigned int*)(pAh + (mb + grp) * 40 + c0);
                ah[mf][1] = *(const unsigned int*)(pAh + (mb + grp + 8) * 40 + c0);
                ah[mf][2] = *(const unsigned int*)(pAh + (mb + grp) * 40 + c0 + 8);
                ah[mf][3] = *(const unsigned int*)(pAh + (mb + grp + 8) * 40 + c0 + 8);
                al[mf][0] = *(const unsigned int*)(pAl + (mb + grp) * 40 + c0);
                al[mf][1] = *(const unsigned int*)(pAl + (mb + grp + 8) * 40 + c0);
                al[mf][2] = *(const unsigned int*)(pAl + (mb + grp) * 40 + c0 + 8);
                al[mf][3] = *(const unsigned int*)(pAl + (mb + grp + 8) * 40 + c0 + 8);
            }
#pragma unroll
            for (int nf = 0; nf < 8; nf++) {
                const int nb = wn * 64 + nf * 8;
                unsigned int bh0 = *(const unsigned int*)(pBh + (nb + grp) * 40 + c0);
                unsigned int bh1 = *(const unsigned int*)(pBh + (nb + grp) * 40 + c0 + 8);
                unsigned int bl0 = *(const unsigned int*)(pBl + (nb + grp) * 40 + c0);
                unsigned int bl1 = *(const unsigned int*)(pBl + (nb + grp) * 40 + c0 + 8);
#pragma unroll
                for (int mf = 0; mf < 2; mf++) {
                    MMA_BF16(acc[mf][nf], ah[mf][0], ah[mf][1], ah[mf][2], ah[mf][3], bh0, bh1);
                    MMA_BF16(acc[mf][nf], ah[mf][0], ah[mf][1], ah[mf][2], ah[mf][3], bl0, bl1);
                    MMA_BF16(acc[mf][nf], al[mf][0], al[mf][1], al[mf][2], al[mf][3], bh0, bh1);
                }
            }
        }
        __syncthreads();
    }

    float* Co = (KS > 1) ? C + (size_t)blockIdx.z * M * Nc : C;
#pragma unroll
    for (int mf = 0; mf < 2; mf++) {
        const int m = row0 + wm * 32 + mf * 16 + grp;
#pragma unroll
        for (int nf = 0; nf < 8; nf++) {
            const int n = col0 + wn * 64 + nf * 8 + thr4 * 2;
            float b0 = 0.f, b1 = 0.f;
            if (bias) { b0 = bias[n]; b1 = bias[n + 1]; }
            float2 v0 = make_float2(acc[mf][nf][0] + b0, acc[mf][nf][1] + b1);
            float2 v1 = make_float2(acc[mf][nf][2] + b0, acc[mf][nf][3] + b1);
            *(float2*)(Co + (size_t)m * Nc + n) = v0;
            *(float2*)(Co + (size_t)(m + 8) * Nc + n) = v1;
        }
    }
}

// ---------------- G pre-split: fp32 -> bf16 hi/lo ------------------------------
__global__ void gsplit_kernel(const float* __restrict__ G,
                              __nv_bfloat16* __restrict__ Gh,
                              __nv_bfloat16* __restrict__ Gl, int sz)
{
    int i = (blockIdx.x * blockDim.x + threadIdx.x) * 4;
    if (i >= sz) return;
    float4 v = *(const float4*)(G + i);
    __nv_bfloat16 h[4], l[4];
    split_bf16(v.x, h[0], l[0]);
    split_bf16(v.y, h[1], l[1]);
    split_bf16(v.z, h[2], l[2]);
    split_bf16(v.w, h[3], l[3]);
    *(__nv_bfloat162*)(Gh + i)     = __halves2bfloat162(h[0], h[1]);
    *(__nv_bfloat162*)(Gh + i + 2) = __halves2bfloat162(h[2], h[3]);
    *(__nv_bfloat162*)(Gl + i)     = __halves2bfloat162(l[0], l[1]);
    *(__nv_bfloat162*)(Gl + i + 2) = __halves2bfloat162(l[2], l[3]);
}

// ---------------- split-K reduce + epilogue (4 partials) ----------------------
__global__ void reduce4_kernel(const float* __restrict__ part, float* __restrict__ C,
                               const float* __restrict__ resid, int do_relu,
                               const float* __restrict__ scale_ptr,
                               __nv_bfloat16* __restrict__ bfh,
                               __nv_bfloat16* __restrict__ bfl)
{
    const int sz = NN * HH;
    int i = (blockIdx.x * blockDim.x + threadIdx.x) * 4;
    if (i >= sz) return;
    float4 a = *(const float4*)(part + i);
    float4 b = *(const float4*)(part + sz + i);
    float4 c = *(const float4*)(part + 2 * sz + i);
    float4 d = *(const float4*)(part + 3 * sz + i);
    float v[4] = {a.x + b.x + c.x + d.x, a.y + b.y + c.y + d.y,
                  a.z + b.z + c.z + d.z, a.w + b.w + c.w + d.w};
    if (resid) {
        float4 r = *(const float4*)(resid + i);
        v[0] += r.x; v[1] += r.y; v[2] += r.z; v[3] += r.w;
    }
    float s = scale_ptr ? *scale_ptr : 1.0f;
#pragma unroll
    for (int j = 0; j < 4; j++) {
        if (do_relu) v[j] = fmaxf(v[j], 0.0f);
        v[j] *= s;
    }
    if (C) *(float4*)(C + i) = make_float4(v[0], v[1], v[2], v[3]);
    if (bfh) {
        __nv_bfloat16 h[4], l[4];
#pragma unroll
        for (int j = 0; j < 4; j++) split_bf16(v[j], h[j], l[j]);
        *(__nv_bfloat162*)(bfh + i)     = __halves2bfloat162(h[0], h[1]);
        *(__nv_bfloat162*)(bfh + i + 2) = __halves2bfloat162(h[2], h[3]);
        *(__nv_bfloat162*)(bfl + i)     = __halves2bfloat162(l[0], l[1]);
        *(__nv_bfloat162*)(bfl + i + 2) = __halves2bfloat162(l[2], l[3]);
    }
}

// ---------------- no-transpose split convert (weights already [Nc][K]) --------
__global__ void convnt_kernel(const float* __restrict__ W,
                              __nv_bfloat16* __restrict__ h,
                              __nv_bfloat16* __restrict__ l, int sz)
{
    int i = blockIdx.x * blockDim.x + threadIdx.x;
    if (i >= sz) return;
    __nv_bfloat16 hh, ll;
    split_bf16(W[i], hh, ll);
    h[i] = hh;
    l[i] = ll;
}

// =======================================================================
// FFMA SGEMM variants (small K=128 weight GEMMs)
// =======================================================================
#define BM 32
#define BK 32

// Shared mainloop body via macro-free duplication (two epilogues).
__global__ __launch_bounds__(256) void sgemm_kernel(
    const float* __restrict__ A, const float* __restrict__ B,
    float* __restrict__ C, int M, int K, int ncols,
    const float* __restrict__ bias)
{
    __shared__ float As[BK][BM];
    __shared__ float Bs[BK][128];

    const int tid = threadIdx.x;
    const int tx = tid & 31;
    const int ty = tid >> 5;
    const int row0 = blockIdx.x * BM;
    const int col0 = blockIdx.y * 128;

    float acc[4][4];
#pragma unroll
    for (int i = 0; i < 4; i++)
#pragma unroll
        for (int j = 0; j < 4; j++) acc[i][j] = 0.0f;

    const int a_row = tid >> 3;
    const int a_k4  = (tid & 7) * 4;
    const int b_c4  = (tid & 31) * 4;
    const int b_kr  = tid >> 5;

    for (int kt = 0; kt < K; kt += BK) {
        float4 a = *(const float4*)(A + (size_t)(row0 + a_row) * K + kt + a_k4);
        As[a_k4 + 0][a_row] = a.x;
        As[a_k4 + 1][a_row] = a.y;
        As[a_k4 + 2][a_row] = a.z;
        As[a_k4 + 3][a_row] = a.w;
#pragma unroll
        for (int i = 0; i < 4; i++) {
            int kr = b_kr + i * 8;
            *(float4*)(&Bs[kr][b_c4]) =
                *(const float4*)(B + (size_t)(kt + kr) * ncols + col0 + b_c4);
        }
        __syncthreads();
#pragma unroll
        for (int k = 0; k < BK; k++) {
            float4 av = *(const float4*)(&As[k][ty * 4]);
            float4 bv = *(const float4*)(&Bs[k][tx * 4]);
            float ar[4] = {av.x, av.y, av.z, av.w};
            float br[4] = {bv.x, bv.y, bv.z, bv.w};
#pragma unroll
            for (int i = 0; i < 4; i++)
#pragma unroll
                for (int j = 0; j < 4; j++)
                    acc[i][j] = fmaf(ar[i], br[j], acc[i][j]);
        }
        __syncthreads();
    }

#pragma unroll
    for (int i = 0; i < 4; i++) {
        const int r = row0 + ty * 4 + i;
        float4 outv;
        float* o = (float*)&outv;
#pragma unroll
        for (int j = 0; j < 4; j++) {
            const int c = col0 + tx * 4 + j;
            o[j] = acc[i][j] + (bias ? bias[c] : 0.0f);
        }
        *(float4*)(C + (size_t)r * ncols + col0 + tx * 4) = outv;
    }
}

// Variant: epilogue writes split-transposed bf16 directly: Bt[c][r], no fp32 out.
__global__ __launch_bounds__(256) void sgemm_bt_kernel(
    const float* __restrict__ A, const float* __restrict__ B,
    __nv_bfloat16* __restrict__ Bth, __nv_bfloat16* __restrict__ Btl,
    int M, int K, int ncols, const float* __restrict__ bias)
{
    __shared__ float As[BK][BM];
    __shared__ float Bs[BK][128];

    const int tid = threadIdx.x;
    const int tx = tid & 31;
    const int ty = tid >> 5;
    const int row0 = blockIdx.x * BM;
    const int col0 = blockIdx.y * 128;

    float acc[4][4];
#pragma unroll
    for (int i = 0; i < 4; i++)
#pragma unroll
        for (int j = 0; j < 4; j++) acc[i][j] = 0.0f;

    const int a_row = tid >> 3;
    const int a_k4  = (tid & 7) * 4;
    const int b_c4  = (tid & 31) * 4;
    const int b_kr  = tid >> 5;

    for (int kt = 0; kt < K; kt += BK) {
        float4 a = *(const float4*)(A + (size_t)(row0 + a_row) * K + kt + a_k4);
        As[a_k4 + 0][a_row] = a.x;
        As[a_k4 + 1][a_row] = a.y;
        As[a_k4 + 2][a_row] = a.z;
        As[a_k4 + 3][a_row] = a.w;
#pragma unroll
        for (int i = 0; i < 4; i++) {
            int kr = b_kr + i * 8;
            *(float4*)(&Bs[kr][b_c4]) =
                *(const float4*)(B + (size_t)(kt + kr) * ncols + col0 + b_c4);
        }
        __syncthreads();
#pragma unroll
        for (int k = 0; k < BK; k++) {
            float4 av = *(const float4*)(&As[k][ty * 4]);
            float4 bv = *(const float4*)(&Bs[k][tx * 4]);
            float ar[4] = {av.x, av.y, av.z, av.w};
            float br[4] = {bv.x, bv.y, bv.z, bv.w};
#pragma unroll
            for (int i = 0; i < 4; i++)
#pragma unroll
                for (int j = 0; j < 4; j++)
                    acc[i][j] = fmaf(ar[i], br[j], acc[i][j]);
        }
        __syncthreads();
    }

    const int r0 = row0 + ty * 4;
#pragma unroll
    for (int j = 0; j < 4; j++) {
        const int c = col0 + tx * 4 + j;
        const float bb = bias ? bias[c] : 0.0f;
        __nv_bfloat16 h[4], l[4];
#pragma unroll
        for (int i = 0; i < 4; i++) split_bf16(acc[i][j] + bb, h[i], l[i]);
        *(__nv_bfloat162*)(Bth + (size_t)c * M + r0)     = __halves2bfloat162(h[0], h[1]);
        *(__nv_bfloat162*)(Bth + (size_t)c * M + r0 + 2) = __halves2bfloat162(h[2], h[3]);
        *(__nv_bfloat162*)(Btl + (size_t)c * M + r0)     = __halves2bfloat162(l[0], l[1]);
        *(__nv_bfloat162*)(Btl + (size_t)c * M + r0 + 2) = __halves2bfloat162(l[2], l[3]);
    }
}

// ---------------- transpose (for Wo only) --------------------------------------
__global__ void transpose_kernel(const float* __restrict__ in, float* __restrict__ out,
                                 int R, int C)
{
    int i = blockIdx.x * blockDim.x + threadIdx.x;
    if (i >= R * C) return;
    int r = i / C, c = i - r * C;
    out[c * R + r] = in[i];
}

// ---------------- mixup combine: bf16 hi/lo output -----------------------------
__global__ void mixcombine_kernel(const float* __restrict__ z1,
                                  const float* __restrict__ z3,
                                  const int* __restrict__ perm,
                                  const float* __restrict__ lam,
                                  __nv_bfloat16* __restrict__ mh,
                                  __nv_bfloat16* __restrict__ ml)
{
    int p = blockIdx.x * blockDim.x + threadIdx.x;     // pair index
    if (p >= NN * HH / 2) return;
    int i = p * 2;
    int b = i >> 7;
    int t = i & 127;
    float l = lam[0];
    int pb = perm[b];
    float v0a = l * z1[i]     + (1.0f - l) * z1[pb * HH + t];
    float v0b = l * z1[i + 1] + (1.0f - l) * z1[pb * HH + t + 1];
    float v1a = l * z3[i]     + (1.0f - l) * z3[pb * HH + t];
    float v1b = l * z3[i + 1] + (1.0f - l) * z3[pb * HH + t + 1];
    __nv_bfloat16 h0a, l0a, h0b, l0b, h1a, l1a, h1b, l1b;
    split_bf16(v0a, h0a, l0a); split_bf16(v0b, h0b, l0b);
    split_bf16(v1a, h1a, l1a); split_bf16(v1b, h1b, l1b);
    *(__nv_bfloat162*)(mh + i) = __halves2bfloat162(h0a, h0b);
    *(__nv_bfloat162*)(ml + i) = __halves2bfloat162(l0a, l0b);
    *(__nv_bfloat162*)(mh + NN * HH + i) = __halves2bfloat162(h1a, h1b);
    *(__nv_bfloat162*)(ml + NN * HH + i) = __halves2bfloat162(l1a, l1b);
}

// ---------------- L=2 self-attention -------------------------------------------
__global__ void attn_kernel(const float* __restrict__ qkv, float* __restrict__ obar,
                            int nh)
{
    int idx = blockIdx.x * blockDim.x + threadIdx.x;
    if (idx >= NN * nh) return;
    int b = idx / nh;
    int h = idx - b * nh;
    int hd = HH / nh;

    const float* base0 = qkv + (size_t)b * 384;
    const float* base1 = qkv + (size_t)NN * 384 + (size_t)b * 384;
    const float* q0 = base0 + h * hd;
    const float* k0 = base0 + 128 + h * hd;
    const float* v0 = base0 + 256 + h * hd;
    const float* q1 = base1 + h * hd;
    const float* k1 = base1 + 128 + h * hd;
    const float* v1 = base1 + 256 + h * hd;

    float s00 = 0.f, s01 = 0.f, s10 = 0.f, s11 = 0.f;
    for (int t = 0; t < hd; t++) {
        float a = q0[t], bq = q1[t], c = k0[t], d = k1[t];
        s00 = fmaf(a, c, s00);
        s01 = fmaf(a, d, s01);
        s10 = fmaf(bq, c, s10);
        s11 = fmaf(bq, d, s11);
    }
    float inv = rsqrtf((float)hd);
    s00 *= inv; s01 *= inv; s10 *= inv; s11 *= inv;

    float m0 = fmaxf(s00, s01);
    float e00 = expf(s00 - m0), e01 = expf(s01 - m0);
    float d0 = e00 + e01;
    float m1 = fmaxf(s10, s11);
    float e10 = expf(s10 - m1), e11 = expf(s11 - m1);
    float d1 = e10 + e11;

    float w0 = 0.5f * (e00 / d0 + e10 / d1);
    float w1 = 0.5f * (e01 / d0 + e11 / d1);

    float* ob = obar + (size_t)b * HH + h * hd;
    for (int t = 0; t < hd; t++)
        ob[t] = w0 * v0[t] + w1 * v1[t];
}

// ---------------- edge head ----------------------------------------------------
__global__ __launch_bounds__(256) void edge_kernel(
    const float* __restrict__ h3, const int* __restrict__ ei,
    const float* __restrict__ Wc, const float* __restrict__ bc,
    float* __restrict__ out)
{
    __shared__ float sWc[512];
    __shared__ float sbc[2];
    for (int i = threadIdx.x; i < 512; i += blockDim.x) sWc[i] = Wc[i];
    if (threadIdx.x < 2) sbc[threadIdx.x] = bc[threadIdx.x];
    __syncthreads();

    int warp = (blockIdx.x * blockDim.x + threadIdx.x) >> 5;
    int lane = threadIdx.x & 31;
    if (warp >= EE) return;

    int src = ei[warp];
    int dst = ei[EE + warp];
    float4 hs = *(const float4*)(h3 + (size_t)src * HH + lane * 4);
    float4 hd4 = *(const float4*)(h3 + (size_t)dst * HH + lane * 4);
    const float* hsp = (const float*)&hs;
    const float* hdp = (const float*)&hd4;

    float a0 = 0.f, a1 = 0.f;
#pragma unroll
    for (int i = 0; i < 4; i++) {
        int rs = lane * 4 + i;
        a0 = fmaf(hsp[i], sWc[rs * 2 + 0], a0);
        a0 = fmaf(hdp[i], sWc[(128 + rs) * 2 + 0], a0);
        a1 = fmaf(hsp[i], sWc[rs * 2 + 1], a1);
        a1 = fmaf(hdp[i], sWc[(128 + rs) * 2 + 1], a1);
    }
#pragma unroll
    for (int off = 16; off; off >>= 1) {
        a0 += __shfl_xor_sync(0xffffffffu, a0, off);
        a1 += __shfl_xor_sync(0xffffffffu, a1, off);
    }
    if (lane == 0) {
        out[(size_t)warp * 2 + 0] = a0 + sbc[0];
        out[(size_t)warp * 2 + 1] = a1 + sbc[1];
    }
}

// ---------------- host orchestration -------------------------------------------
static inline void tgemm(const __nv_bfloat16* Ah, const __nv_bfloat16* Al,
                         const __nv_bfloat16* Bh, const __nv_bfloat16* Bl,
                         float* C, int M, int K, int Nc, const float* bias, int KS)
{
    dim3 grid(M / 128, Nc / 128, KS);
    tgemm_kernel<<<grid, 256, TGEMM_SMEM>>>(Ah, Al, Bh, Bl, C, M, K, Nc, bias);
}

extern "C" void kernel_launch(void* const* d_in, const int* in_sizes, int n_in,
                              void* d_out, int out_size)
{
    const float* x     = (const float*)d_in[0];
    const float* G1    = (const float*)d_in[1];
    const float* G3    = (const float*)d_in[2];
    const int*   ei    = (const int*)d_in[3];
    const int*   perm  = (const int*)d_in[4];
    const float* lam   = (const float*)d_in[5];
    const float* beta  = (const float*)d_in[6];
    const float* W1    = (const float*)d_in[7];  const float* b1   = (const float*)d_in[8];
    const float* W2    = (const float*)d_in[9];  const float* b2   = (const float*)d_in[10];
    const float* W3    = (const float*)d_in[11]; const float* b3   = (const float*)d_in[12];
    const float* W1h   = (const float*)d_in[13]; const float* b1h  = (const float*)d_in[14];
    const float* W3h   = (const float*)d_in[15]; const float* b3h  = (const float*)d_in[16];
    const float* W2m   = (const float*)d_in[17]; const float* b2m  = (const float*)d_in[18];
    const float* W3m   = (const float*)d_in[19]; const float* b3m  = (const float*)d_in[20];
    const float* WqkvM = (const float*)d_in[21]; const float* bqkvM= (const float*)d_in[22];
    const float* WoM   = (const float*)d_in[23]; const float* boM  = (const float*)d_in[24];
    const float* WqkvF = (const float*)d_in[25]; const float* bqkvF= (const float*)d_in[26];
    const float* WoF   = (const float*)d_in[27]; const float* boF  = (const float*)d_in[28];
    const float* Wc    = (const float*)d_in[29]; const float* bc   = (const float*)d_in[30];

    float *h1, *h2, *z1, *z3, *qkv, *obar, *h1mix, *ToM, *ToF, *part;
    __nv_bfloat16 *G1h, *G1l, *G3h, *G3l, *BtYh, *BtYl, *BtWh, *BtWl;
    __nv_bfloat16 *mixh, *mixl, *fush, *fusl;
    cudaGetSymbolAddress((void**)&h1,    g_h1);
    cudaGetSymbolAddress((void**)&h2,    g_h2);
    cudaGetSymbolAddress((void**)&z1,    g_z1);
    cudaGetSymbolAddress((void**)&z3,    g_z3);
    cudaGetSymbolAddress((void**)&qkv,   g_qkv);
    cudaGetSymbolAddress((void**)&obar,  g_obar);
    cudaGetSymbolAddress((void**)&h1mix, g_h1mix);
    cudaGetSymbolAddress((void**)&ToM,   g_ToM);
    cudaGetSymbolAddress((void**)&ToF,   g_ToF);
    cudaGetSymbolAddress((void**)&part,  g_part);
    cudaGetSymbolAddress((void**)&G1h,   g_G1h);
    cudaGetSymbolAddress((void**)&G1l,   g_G1l);
    cudaGetSymbolAddress((void**)&G3h,   g_G3h);
    cudaGetSymbolAddress((void**)&G3l,   g_G3l);
    cudaGetSymbolAddress((void**)&BtYh,  g_BtYh);
    cudaGetSymbolAddress((void**)&BtYl,  g_BtYl);
    cudaGetSymbolAddress((void**)&BtWh,  g_BtWh);
    cudaGetSymbolAddress((void**)&BtWl,  g_BtWl);
    cudaGetSymbolAddress((void**)&mixh,  g_mixh);
    cudaGetSymbolAddress((void**)&mixl,  g_mixl);
    cudaGetSymbolAddress((void**)&fush,  g_fush);
    cudaGetSymbolAddress((void**)&fusl,  g_fusl);

    cudaFuncSetAttribute(tgemm_kernel, cudaFuncAttributeMaxDynamicSharedMemorySize,
                         TGEMM_SMEM);

    float* out = (float*)d_out;
    float* h3  = out + (size_t)EE * 2;

    const int red_grid = (NN * HH / 4 + 255) / 256;
    const dim3 sg_grid(NN / BM, 1);

    // one-time conversions
    gsplit_kernel<<<(NN * NN / 4 + 255) / 256, 256>>>(G1, G1h, G1l, NN * NN);
    gsplit_kernel<<<(NN * NN / 4 + 255) / 256, 256>>>(G3, G3h, G3l, NN * NN);
    transpose_kernel<<<(HH * HH + 255) / 256, 256>>>(WoM, ToM, HH, HH);
    transpose_kernel<<<(HH * HH + 255) / 256, 256>>>(WoF, ToF, HH, HH);

    // h1 = relu(G1 @ (x W1 + b1))
    sgemm_bt_kernel<<<sg_grid, 256>>>(x, W1, BtYh, BtYl, NN, HH, HH, b1);
    tgemm(G1h, G1l, BtYh, BtYl, part, NN, NN, HH, nullptr, 4);
    reduce4_kernel<<<red_grid, 256>>>(part, h1, nullptr, 1, nullptr, nullptr, nullptr);

    // h2 = relu(G1 @ (h1 W2 + b2) + h1)
    sgemm_bt_kernel<<<sg_grid, 256>>>(h1, W2, BtYh, BtYl, NN, HH, HH, b2);
    tgemm(G1h, G1l, BtYh, BtYl, part, NN, NN, HH, nullptr, 4);
    reduce4_kernel<<<red_grid, 256>>>(part, h2, h1, 1, nullptr, nullptr, nullptr);

    // h3_c1 -> fus[0] (bf16 only)
    sgemm_bt_kernel<<<sg_grid, 256>>>(h2, W3, BtYh, BtYl, NN, HH, HH, b3);
    tgemm(G1h, G1l, BtYh, BtYl, part, NN, NN, HH, nullptr, 4);
    reduce4_kernel<<<red_grid, 256>>>(part, nullptr, h2, 1, nullptr, fush, fusl);

    // z1 = G1 @ (h1 W1h + b1h)
    sgemm_bt_kernel<<<sg_grid, 256>>>(h1, W1h, BtYh, BtYl, NN, HH, HH, b1h);
    tgemm(G1h, G1l, BtYh, BtYl, part, NN, NN, HH, nullptr, 4);
    reduce4_kernel<<<red_grid, 256>>>(part, z1, nullptr, 0, nullptr, nullptr, nullptr);

    // z3 = G3 @ (h1 W3h + b3h)
    sgemm_bt_kernel<<<sg_grid, 256>>>(h1, W3h, BtYh, BtYl, NN, HH, HH, b3h);
    tgemm(G3h, G3l, BtYh, BtYl, part, NN, NN, HH, nullptr, 4);
    reduce4_kernel<<<red_grid, 256>>>(part, z3, nullptr, 0, nullptr, nullptr, nullptr);

    // mixup (permuted-graph term == z[perm]); emits bf16 hi/lo stack
    mixcombine_kernel<<<(NN * HH / 2 + 255) / 256, 256>>>(z1, z3, perm, lam, mixh, mixl);

    // MHA mix (nh=2)
    convnt_kernel<<<(3 * HH * HH + 255) / 256, 256>>>(WqkvM, BtWh, BtWl, 3 * HH * HH);
    tgemm(mixh, mixl, BtWh, BtWl, qkv, 2 * NN, HH, 3 * HH, bqkvM, 1);
    attn_kernel<<<(NN * 2 + 255) / 256, 256>>>(qkv, obar, 2);
    sgemm_kernel<<<sg_grid, 256>>>(obar, ToM, h1mix, NN, HH, HH, boM);

    // h2_mix = relu(G1 @ (h1mix W2m + b2m) + h1mix)
    sgemm_bt_kernel<<<sg_grid, 256>>>(h1mix, W2m, BtYh, BtYl, NN, HH, HH, b2m);
    tgemm(G1h, G1l, BtYh, BtYl, part, NN, NN, HH, nullptr, 4);
    reduce4_kernel<<<red_grid, 256>>>(part, h2, h1mix, 1, nullptr, nullptr, nullptr);

    // h3_c2 = relu(G1 @ (h2mix W3m + b3m) + h2mix) * beta -> fus[1] (bf16 only)
    sgemm_bt_kernel<<<sg_grid, 256>>>(h2, W3m, BtYh, BtYl, NN, HH, HH, b3m);
    tgemm(G1h, G1l, BtYh, BtYl, part, NN, NN, HH, nullptr, 4);
    reduce4_kernel<<<red_grid, 256>>>(part, nullptr, h2, 1, beta,
                                      fush + (size_t)NN * HH, fusl + (size_t)NN * HH);

    // MHA fus (nh=4)
    convnt_kernel<<<(3 * HH * HH + 255) / 256, 256>>>(WqkvF, BtWh, BtWl, 3 * HH * HH);
    tgemm(fush, fusl, BtWh, BtWl, qkv, 2 * NN, HH, 3 * HH, bqkvF, 1);
    attn_kernel<<<(NN * 4 + 255) / 256, 256>>>(qkv, obar, 4);
    sgemm_kernel<<<sg_grid, 256>>>(obar, ToF, h3, NN, HH, HH, boF);

    // edge predictions
    edge_kernel<<<EE / 8, 256>>>(h3, ei, Wc, bc, out);
}

// round 7
// speedup vs baseline: 1.5141x; 1.5141x over previous
#include <cuda_runtime.h>
#include <cuda_bf16.h>
#include <cstdint>
#include <math.h>

// Problem constants
#define NN 4096
#define HH 128
#define EE 131072

// ---------------- scratch (static device arrays; no allocation) ----------------
__device__ float g_h1[NN * HH];
__device__ float g_h2[NN * HH];
__device__ float g_z1[NN * HH];
__device__ float g_z3[NN * HH];
__device__ float g_qkv[2 * NN * 3 * HH];
__device__ float g_obar[NN * HH];
__device__ float g_h1mix[NN * HH];
__device__ float g_ToM[HH * HH];
__device__ float g_ToF[HH * HH];
__device__ float g_part[4 * NN * HH];                 // split-K partials
__device__ __nv_bfloat16 g_G1h[NN * NN];              // pre-split G1 hi
__device__ __nv_bfloat16 g_G1l[NN * NN];              // pre-split G1 lo
__device__ __nv_bfloat16 g_G3h[NN * NN];
__device__ __nv_bfloat16 g_G3l[NN * NN];
__device__ __nv_bfloat16 g_BtYh[HH * NN];             // Y^T hi  [128][4096]
__device__ __nv_bfloat16 g_BtYl[HH * NN];
__device__ __nv_bfloat16 g_BtWh[3 * HH * HH];         // weight Bt hi (max 384x128)
__device__ __nv_bfloat16 g_BtWl[3 * HH * HH];
__device__ __nv_bfloat16 g_mixh[2 * NN * HH];
__device__ __nv_bfloat16 g_mixl[2 * NN * HH];
__device__ __nv_bfloat16 g_fush[2 * NN * HH];
__device__ __nv_bfloat16 g_fusl[2 * NN * HH];

// ---------------- helpers -------------------------------------------------------
__device__ __forceinline__ void split_bf16(float v, __nv_bfloat16& h, __nv_bfloat16& l)
{
    h = __float2bfloat16(v);
    l = __float2bfloat16(v - __bfloat162float(h));
}

#define MMA_BF16(d, a0, a1, a2, a3, b0, b1)                                   \
    asm volatile(                                                             \
        "mma.sync.aligned.m16n8k16.row.col.f32.bf16.bf16.f32 "                \
        "{%0,%1,%2,%3}, {%4,%5,%6,%7}, {%8,%9}, {%0,%1,%2,%3};"               \
        : "+f"(d[0]), "+f"(d[1]), "+f"(d[2]), "+f"(d[3])                      \
        : "r"(a0), "r"(a1), "r"(a2), "r"(a3), "r"(b0), "r"(b1))

// =======================================================================
// Tensor-core GEMM (legacy mma.sync): C[M,Nc] = A[M,K] @ B[K,Nc]
//   A pre-split bf16 hi/lo row-major [M][K]; B pre-split transposed [Nc][K].
//   Emulated fp32: Ah*Bh + Ah*Bl + Al*Bh (fp32 accumulate).
//   grid (M/128, Nc/128, KS). KS>1 -> partials at C + z*M*Nc (no bias).
//   Single-buffered static smem, register prefetch (R2-proven structure).
// =======================================================================
__global__ __launch_bounds__(256) void tgemm_kernel(
    const __nv_bfloat16* __restrict__ Ah, const __nv_bfloat16* __restrict__ Al,
    const __nv_bfloat16* __restrict__ Bh, const __nv_bfloat16* __restrict__ Bl,
    float* __restrict__ C, int M, int K, int Nc,
    const float* __restrict__ bias)
{
    __shared__ __nv_bfloat16 sAh[128][40];
    __shared__ __nv_bfloat16 sAl[128][40];
    __shared__ __nv_bfloat16 sBh[128][40];
    __shared__ __nv_bfloat16 sBl[128][40];

    const int tid  = threadIdx.x;
    const int row0 = blockIdx.x * 128;
    const int col0 = blockIdx.y * 128;
    const int KS     = gridDim.z;
    const int kiters = K / (32 * KS);
    const int kbase  = blockIdx.z * kiters * 32;

    const int warp = tid >> 5, lane = tid & 31;
    const int wm = warp & 3, wn = warp >> 2;          // 4 x 2 warp grid
    const int grp = lane >> 2, thr4 = lane & 3;

    float acc[2][8][4];
#pragma unroll
    for (int mf = 0; mf < 2; mf++)
#pragma unroll
        for (int nf = 0; nf < 8; nf++)
#pragma unroll
            for (int i = 0; i < 4; i++) acc[mf][nf][i] = 0.0f;

    // loader: row = tid>>1, 16-elem half = (tid&1)*16; 2 x uint4 per array
    const int l_r = tid >> 1;
    const int l_c = (tid & 1) * 16;
    const __nv_bfloat16* gAh = Ah + (size_t)(row0 + l_r) * K + kbase + l_c;
    const __nv_bfloat16* gAl = Al + (size_t)(row0 + l_r) * K + kbase + l_c;
    const __nv_bfloat16* gBh = Bh + (size_t)(col0 + l_r) * K + kbase + l_c;
    const __nv_bfloat16* gBl = Bl + (size_t)(col0 + l_r) * K + kbase + l_c;

    uint4 pah[2], pal[2], pbh[2], pbl[2];

    // prefetch tile 0
#pragma unroll
    for (int i = 0; i < 2; i++) {
        pah[i] = *(const uint4*)(gAh + i * 8);
        pal[i] = *(const uint4*)(gAl + i * 8);
        pbh[i] = *(const uint4*)(gBh + i * 8);
        pbl[i] = *(const uint4*)(gBl + i * 8);
    }

    for (int it = 0; it < kiters; it++) {
        // ---- store prefetched tile into smem ----
        *(uint4*)&sAh[l_r][l_c]     = pah[0];
        *(uint4*)&sAh[l_r][l_c + 8] = pah[1];
        *(uint4*)&sAl[l_r][l_c]     = pal[0];
        *(uint4*)&sAl[l_r][l_c + 8] = pal[1];
        *(uint4*)&sBh[l_r][l_c]     = pbh[0];
        *(uint4*)&sBh[l_r][l_c + 8] = pbh[1];
        *(uint4*)&sBl[l_r][l_c]     = pbl[0];
        *(uint4*)&sBl[l_r][l_c + 8] = pbl[1];
        __syncthreads();

        // ---- prefetch next tile ----
        if (it + 1 < kiters) {
            const int ko = (it + 1) * 32;
#pragma unroll
            for (int i = 0; i < 2; i++) {
                pah[i] = *(const uint4*)(gAh + ko + i * 8);
                pal[i] = *(const uint4*)(gAl + ko + i * 8);
                pbh[i] = *(const uint4*)(gBh + ko + i * 8);
                pbl[i] = *(const uint4*)(gBl + ko + i * 8);
            }
        }

        // ---- compute ----
#pragma unroll
        for (int koff = 0; koff < 32; koff += 16) {
            unsigned int ah[2][4], al[2][4];
            const int c0 = koff + thr4 * 2;
#pragma unroll
            for (int mf = 0; mf < 2; mf++) {
                const int mb = wm * 32 + mf * 16;
                ah[mf][0] = *(const unsigned int*)&sAh[mb + grp][c0];
                ah[mf][1] = *(const unsigned int*)&sAh[mb + grp + 8][c0];
                ah[mf][2] = *(const unsigned int*)&sAh[mb + grp][c0 + 8];
                ah[mf][3] = *(const unsigned int*)&sAh[mb + grp + 8][c0 + 8];
                al[mf][0] = *(const unsigned int*)&sAl[mb + grp][c0];
                al[mf][1] = *(const unsigned int*)&sAl[mb + grp + 8][c0];
                al[mf][2] = *(const unsigned int*)&sAl[mb + grp][c0 + 8];
                al[mf][3] = *(const unsigned int*)&sAl[mb + grp + 8][c0 + 8];
            }
#pragma unroll
            for (int nf = 0; nf < 8; nf++) {
                const int nb = wn * 64 + nf * 8;
                unsigned int bh0 = *(const unsigned int*)&sBh[nb + grp][c0];
                unsigned int bh1 = *(const unsigned int*)&sBh[nb + grp][c0 + 8];
                unsigned int bl0 = *(const unsigned int*)&sBl[nb + grp][c0];
                unsigned int bl1 = *(const unsigned int*)&sBl[nb + grp][c0 + 8];
#pragma unroll
                for (int mf = 0; mf < 2; mf++) {
                    MMA_BF16(acc[mf][nf], ah[mf][0], ah[mf][1], ah[mf][2], ah[mf][3], bh0, bh1);
                    MMA_BF16(acc[mf][nf], ah[mf][0], ah[mf][1], ah[mf][2], ah[mf][3], bl0, bl1);
                    MMA_BF16(acc[mf][nf], al[mf][0], al[mf][1], al[mf][2], al[mf][3], bh0, bh1);
                }
            }
        }
        __syncthreads();
    }

    // ---- epilogue ----
    float* Co = (KS > 1) ? C + (size_t)blockIdx.z * M * Nc : C;
#pragma unroll
    for (int mf = 0; mf < 2; mf++) {
        const int m = row0 + wm * 32 + mf * 16 + grp;
#pragma unroll
        for (int nf = 0; nf < 8; nf++) {
            const int n = col0 + wn * 64 + nf * 8 + thr4 * 2;
            float b0 = 0.f, b1 = 0.f;
            if (bias) { b0 = bias[n]; b1 = bias[n + 1]; }
            float2 v0 = make_float2(acc[mf][nf][0] + b0, acc[mf][nf][1] + b1);
            float2 v1 = make_float2(acc[mf][nf][2] + b0, acc[mf][nf][3] + b1);
            *(float2*)(Co + (size_t)m * Nc + n) = v0;
            *(float2*)(Co + (size_t)(m + 8) * Nc + n) = v1;
        }
    }
}

// ---------------- G pre-split: fp32 -> bf16 hi/lo ------------------------------
__global__ void gsplit_kernel(const float* __restrict__ G,
                              __nv_bfloat16* __restrict__ Gh,
                              __nv_bfloat16* __restrict__ Gl, int sz)
{
    int i = (blockIdx.x * blockDim.x + threadIdx.x) * 4;
    if (i >= sz) return;
    float4 v = *(const float4*)(G + i);
    __nv_bfloat16 h[4], l[4];
    split_bf16(v.x, h[0], l[0]);
    split_bf16(v.y, h[1], l[1]);
    split_bf16(v.z, h[2], l[2]);
    split_bf16(v.w, h[3], l[3]);
    *(__nv_bfloat162*)(Gh + i)     = __halves2bfloat162(h[0], h[1]);
    *(__nv_bfloat162*)(Gh + i + 2) = __halves2bfloat162(h[2], h[3]);
    *(__nv_bfloat162*)(Gl + i)     = __halves2bfloat162(l[0], l[1]);
    *(__nv_bfloat162*)(Gl + i + 2) = __halves2bfloat162(l[2], l[3]);
}

// ---------------- split-K reduce + epilogue (4 partials) ----------------------
__global__ void reduce4_kernel(const float* __restrict__ part, float* __restrict__ C,
                               const float* __restrict__ resid, int do_relu,
                               const float* __restrict__ scale_ptr,
                               __nv_bfloat16* __restrict__ bfh,
                               __nv_bfloat16* __restrict__ bfl)
{
    const int sz = NN * HH;
    int i = (blockIdx.x * blockDim.x + threadIdx.x) * 4;
    if (i >= sz) return;
    float4 a = *(const float4*)(part + i);
    float4 b = *(const float4*)(part + sz + i);
    float4 c = *(const float4*)(part + 2 * sz + i);
    float4 d = *(const float4*)(part + 3 * sz + i);
    float v[4] = {a.x + b.x + c.x + d.x, a.y + b.y + c.y + d.y,
                  a.z + b.z + c.z + d.z, a.w + b.w + c.w + d.w};
    if (resid) {
        float4 r = *(const float4*)(resid + i);
        v[0] += r.x; v[1] += r.y; v[2] += r.z; v[3] += r.w;
    }
    float s = scale_ptr ? *scale_ptr : 1.0f;
#pragma unroll
    for (int j = 0; j < 4; j++) {
        if (do_relu) v[j] = fmaxf(v[j], 0.0f);
        v[j] *= s;
    }
    if (C) *(float4*)(C + i) = make_float4(v[0], v[1], v[2], v[3]);
    if (bfh) {
        __nv_bfloat16 h[4], l[4];
#pragma unroll
        for (int j = 0; j < 4; j++) split_bf16(v[j], h[j], l[j]);
        *(__nv_bfloat162*)(bfh + i)     = __halves2bfloat162(h[0], h[1]);
        *(__nv_bfloat162*)(bfh + i + 2) = __halves2bfloat162(h[2], h[3]);
        *(__nv_bfloat162*)(bfl + i)     = __halves2bfloat162(l[0], l[1]);
        *(__nv_bfloat162*)(bfl + i + 2) = __halves2bfloat162(l[2], l[3]);
    }
}

// ---------------- no-transpose split convert (weights already [Nc][K]) --------
__global__ void convnt_kernel(const float* __restrict__ W,
                              __nv_bfloat16* __restrict__ h,
                              __nv_bfloat16* __restrict__ l, int sz)
{
    int i = blockIdx.x * blockDim.x + threadIdx.x;
    if (i >= sz) return;
    __nv_bfloat16 hh, ll;
    split_bf16(W[i], hh, ll);
    h[i] = hh;
    l[i] = ll;
}

// =======================================================================
// FFMA SGEMM variants (small K=128 weight GEMMs)
// =======================================================================
#define BM 32
#define BK 32

__global__ __launch_bounds__(256) void sgemm_kernel(
    const float* __restrict__ A, const float* __restrict__ B,
    float* __restrict__ C, int M, int K, int ncols,
    const float* __restrict__ bias)
{
    __shared__ float As[BK][BM];
    __shared__ float Bs[BK][128];

    const int tid = threadIdx.x;
    const int tx = tid & 31;
    const int ty = tid >> 5;
    const int row0 = blockIdx.x * BM;
    const int col0 = blockIdx.y * 128;

    float acc[4][4];
#pragma unroll
    for (int i = 0; i < 4; i++)
#pragma unroll
        for (int j = 0; j < 4; j++) acc[i][j] = 0.0f;

    const int a_row = tid >> 3;
    const int a_k4  = (tid & 7) * 4;
    const int b_c4  = (tid & 31) * 4;
    const int b_kr  = tid >> 5;

    for (int kt = 0; kt < K; kt += BK) {
        float4 a = *(const float4*)(A + (size_t)(row0 + a_row) * K + kt + a_k4);
        As[a_k4 + 0][a_row] = a.x;
        As[a_k4 + 1][a_row] = a.y;
        As[a_k4 + 2][a_row] = a.z;
        As[a_k4 + 3][a_row] = a.w;
#pragma unroll
        for (int i = 0; i < 4; i++) {
            int kr = b_kr + i * 8;
            *(float4*)(&Bs[kr][b_c4]) =
                *(const float4*)(B + (size_t)(kt + kr) * ncols + col0 + b_c4);
        }
        __syncthreads();
#pragma unroll
        for (int k = 0; k < BK; k++) {
            float4 av = *(const float4*)(&As[k][ty * 4]);
            float4 bv = *(const float4*)(&Bs[k][tx * 4]);
            float ar[4] = {av.x, av.y, av.z, av.w};
            float br[4] = {bv.x, bv.y, bv.z, bv.w};
#pragma unroll
            for (int i = 0; i < 4; i++)
#pragma unroll
                for (int j = 0; j < 4; j++)
                    acc[i][j] = fmaf(ar[i], br[j], acc[i][j]);
        }
        __syncthreads();
    }

#pragma unroll
    for (int i = 0; i < 4; i++) {
        const int r = row0 + ty * 4 + i;
        float4 outv;
        float* o = (float*)&outv;
#pragma unroll
        for (int j = 0; j < 4; j++) {
            const int c = col0 + tx * 4 + j;
            o[j] = acc[i][j] + (bias ? bias[c] : 0.0f);
        }
        *(float4*)(C + (size_t)r * ncols + col0 + tx * 4) = outv;
    }
}

// Variant: epilogue writes split-transposed bf16 directly: Bt[c][r].
__global__ __launch_bounds__(256) void sgemm_bt_kernel(
    const float* __restrict__ A, const float* __restrict__ B,
    __nv_bfloat16* __restrict__ Bth, __nv_bfloat16* __restrict__ Btl,
    int M, int K, int ncols, const float* __restrict__ bias)
{
    __shared__ float As[BK][BM];
    __shared__ float Bs[BK][128];

    const int tid = threadIdx.x;
    const int tx = tid & 31;
    const int ty = tid >> 5;
    const int row0 = blockIdx.x * BM;
    const int col0 = blockIdx.y * 128;

    float acc[4][4];
#pragma unroll
    for (int i = 0; i < 4; i++)
#pragma unroll
        for (int j = 0; j < 4; j++) acc[i][j] = 0.0f;

    const int a_row = tid >> 3;
    const int a_k4  = (tid & 7) * 4;
    const int b_c4  = (tid & 31) * 4;
    const int b_kr  = tid >> 5;

    for (int kt = 0; kt < K; kt += BK) {
        float4 a = *(const float4*)(A + (size_t)(row0 + a_row) * K + kt + a_k4);
        As[a_k4 + 0][a_row] = a.x;
        As[a_k4 + 1][a_row] = a.y;
        As[a_k4 + 2][a_row] = a.z;
        As[a_k4 + 3][a_row] = a.w;
#pragma unroll
        for (int i = 0; i < 4; i++) {
            int kr = b_kr + i * 8;
            *(float4*)(&Bs[kr][b_c4]) =
                *(const float4*)(B + (size_t)(kt + kr) * ncols + col0 + b_c4);
        }
        __syncthreads();
#pragma unroll
        for (int k = 0; k < BK; k++) {
            float4 av = *(const float4*)(&As[k][ty * 4]);
            float4 bv = *(const float4*)(&Bs[k][tx * 4]);
            float ar[4] = {av.x, av.y, av.z, av.w};
            float br[4] = {bv.x, bv.y, bv.z, bv.w};
#pragma unroll
            for (int i = 0; i < 4; i++)
#pragma unroll
                for (int j = 0; j < 4; j++)
                    acc[i][j] = fmaf(ar[i], br[j], acc[i][j]);
        }
        __syncthreads();
    }

    const int r0 = row0 + ty * 4;
#pragma unroll
    for (int j = 0; j < 4; j++) {
        const int c = col0 + tx * 4 + j;
        const float bb = bias ? bias[c] : 0.0f;
        __nv_bfloat16 h[4], l[4];
#pragma unroll
        for (int i = 0; i < 4; i++) split_bf16(acc[i][j] + bb, h[i], l[i]);
        *(__nv_bfloat162*)(Bth + (size_t)c * M + r0)     = __halves2bfloat162(h[0], h[1]);
        *(__nv_bfloat162*)(Bth + (size_t)c * M + r0 + 2) = __halves2bfloat162(h[2], h[3]);
        *(__nv_bfloat162*)(Btl + (size_t)c * M + r0)     = __halves2bfloat162(l[0], l[1]);
        *(__nv_bfloat162*)(Btl + (size_t)c * M + r0 + 2) = __halves2bfloat162(l[2], l[3]);
    }
}

// ---------------- transpose (for Wo only) --------------------------------------
__global__ void transpose_kernel(const float* __restrict__ in, float* __restrict__ out,
                                 int R, int C)
{
    int i = blockIdx.x * blockDim.x + threadIdx.x;
    if (i >= R * C) return;
    int r = i / C, c = i - r * C;
    out[c * R + r] = in[i];
}

// ---------------- mixup combine: bf16 hi/lo output -----------------------------
__global__ void mixcombine_kernel(const float* __restrict__ z1,
                                  const float* __restrict__ z3,
                                  const int* __restrict__ perm,
                                  const float* __restrict__ lam,
                                  __nv_bfloat16* __restrict__ mh,
                                  __nv_bfloat16* __restrict__ ml)
{
    int p = blockIdx.x * blockDim.x + threadIdx.x;
    if (p >= NN * HH / 2) return;
    int i = p * 2;
    int b = i >> 7;
    int t = i & 127;
    float l = lam[0];
    int pb = perm[b];
    float v0a = l * z1[i]     + (1.0f - l) * z1[pb * HH + t];
    float v0b = l * z1[i + 1] + (1.0f - l) * z1[pb * HH + t + 1];
    float v1a = l * z3[i]     + (1.0f - l) * z3[pb * HH + t];
    float v1b = l * z3[i + 1] + (1.0f - l) * z3[pb * HH + t + 1];
    __nv_bfloat16 h0a, l0a, h0b, l0b, h1a, l1a, h1b, l1b;
    split_bf16(v0a, h0a, l0a); split_bf16(v0b, h0b, l0b);
    split_bf16(v1a, h1a, l1a); split_bf16(v1b, h1b, l1b);
    *(__nv_bfloat162*)(mh + i) = __halves2bfloat162(h0a, h0b);
    *(__nv_bfloat162*)(ml + i) = __halves2bfloat162(l0a, l0b);
    *(__nv_bfloat162*)(mh + NN * HH + i) = __halves2bfloat162(h1a, h1b);
    *(__nv_bfloat162*)(ml + NN * HH + i) = __halves2bfloat162(l1a, l1b);
}

// ---------------- L=2 self-attention -------------------------------------------
__global__ void attn_kernel(const float* __restrict__ qkv, float* __restrict__ obar,
                            int nh)
{
    int idx = blockIdx.x * blockDim.x + threadIdx.x;
    if (idx >= NN * nh) return;
    int b = idx / nh;
    int h = idx - b * nh;
    int hd = HH / nh;

    const float* base0 = qkv + (size_t)b * 384;
    const float* base1 = qkv + (size_t)NN * 384 + (size_t)b * 384;
    const float* q0 = base0 + h * hd;
    const float* k0 = base0 + 128 + h * hd;
    const float* v0 = base0 + 256 + h * hd;
    const float* q1 = base1 + h * hd;
    const float* k1 = base1 + 128 + h * hd;
    const float* v1 = base1 + 256 + h * hd;

    float s00 = 0.f, s01 = 0.f, s10 = 0.f, s11 = 0.f;
    for (int t = 0; t < hd; t++) {
        float a = q0[t], bq = q1[t], c = k0[t], d = k1[t];
        s00 = fmaf(a, c, s00);
        s01 = fmaf(a, d, s01);
        s10 = fmaf(bq, c, s10);
        s11 = fmaf(bq, d, s11);
    }
    float inv = rsqrtf((float)hd);
    s00 *= inv; s01 *= inv; s10 *= inv; s11 *= inv;

    float m0 = fmaxf(s00, s01);
    float e00 = expf(s00 - m0), e01 = expf(s01 - m0);
    float d0 = e00 + e01;
    float m1 = fmaxf(s10, s11);
    float e10 = expf(s10 - m1), e11 = expf(s11 - m1);
    float d1 = e10 + e11;

    float w0 = 0.5f * (e00 / d0 + e10 / d1);
    float w1 = 0.5f * (e01 / d0 + e11 / d1);

    float* ob = obar + (size_t)b * HH + h * hd;
    for (int t = 0; t < hd; t++)
        ob[t] = w0 * v0[t] + w1 * v1[t];
}

// ---------------- edge head ----------------------------------------------------
__global__ __launch_bounds__(256) void edge_kernel(
    const float* __restrict__ h3, const int* __restrict__ ei,
    const float* __restrict__ Wc, const float* __restrict__ bc,
    float* __restrict__ out)
{
    __shared__ float sWc[512];
    __shared__ float sbc[2];
    for (int i = threadIdx.x; i < 512; i += blockDim.x) sWc[i] = Wc[i];
    if (threadIdx.x < 2) sbc[threadIdx.x] = bc[threadIdx.x];
    __syncthreads();

    int warp = (blockIdx.x * blockDim.x + threadIdx.x) >> 5;
    int lane = threadIdx.x & 31;
    if (warp >= EE) return;

    int src = ei[warp];
    int dst = ei[EE + warp];
    float4 hs = *(const float4*)(h3 + (size_t)src * HH + lane * 4);
    float4 hd4 = *(const float4*)(h3 + (size_t)dst * HH + lane * 4);
    const float* hsp = (const float*)&hs;
    const float* hdp = (const float*)&hd4;

    float a0 = 0.f, a1 = 0.f;
#pragma unroll
    for (int i = 0; i < 4; i++) {
        int rs = lane * 4 + i;
        a0 = fmaf(hsp[i], sWc[rs * 2 + 0], a0);
        a0 = fmaf(hdp[i], sWc[(128 + rs) * 2 + 0], a0);
        a1 = fmaf(hsp[i], sWc[rs * 2 + 1], a1);
        a1 = fmaf(hdp[i], sWc[(128 + rs) * 2 + 1], a1);
    }
#pragma unroll
    for (int off = 16; off; off >>= 1) {
        a0 += __shfl_xor_sync(0xffffffffu, a0, off);
        a1 += __shfl_xor_sync(0xffffffffu, a1, off);
    }
    if (lane == 0) {
        out[(size_t)warp * 2 + 0] = a0 + sbc[0];
        out[(size_t)warp * 2 + 1] = a1 + sbc[1];
    }
}

// ---------------- host orchestration -------------------------------------------
static inline void tgemm(const __nv_bfloat16* Ah, const __nv_bfloat16* Al,
                         const __nv_bfloat16* Bh, const __nv_bfloat16* Bl,
                         float* C, int M, int K, int Nc, const float* bias, int KS)
{
    dim3 grid(M / 128, Nc / 128, KS);
    tgemm_kernel<<<grid, 256>>>(Ah, Al, Bh, Bl, C, M, K, Nc, bias);
}

extern "C" void kernel_launch(void* const* d_in, const int* in_sizes, int n_in,
                              void* d_out, int out_size)
{
    const float* x     = (const float*)d_in[0];
    const float* G1    = (const float*)d_in[1];
    const float* G3    = (const float*)d_in[2];
    const int*   ei    = (const int*)d_in[3];
    const int*   perm  = (const int*)d_in[4];
    const float* lam   = (const float*)d_in[5];
    const float* beta  = (const float*)d_in[6];
    const float* W1    = (const float*)d_in[7];  const float* b1   = (const float*)d_in[8];
    const float* W2    = (const float*)d_in[9];  const float* b2   = (const float*)d_in[10];
    const float* W3    = (const float*)d_in[11]; const float* b3   = (const float*)d_in[12];
    const float* W1h   = (const float*)d_in[13]; const float* b1h  = (const float*)d_in[14];
    const float* W3h   = (const float*)d_in[15]; const float* b3h  = (const float*)d_in[16];
    const float* W2m   = (const float*)d_in[17]; const float* b2m  = (const float*)d_in[18];
    const float* W3m   = (const float*)d_in[19]; const float* b3m  = (const float*)d_in[20];
    const float* WqkvM = (const float*)d_in[21]; const float* bqkvM= (const float*)d_in[22];
    const float* WoM   = (const float*)d_in[23]; const float* boM  = (const float*)d_in[24];
    const float* WqkvF = (const float*)d_in[25]; const float* bqkvF= (const float*)d_in[26];
    const float* WoF   = (const float*)d_in[27]; const float* boF  = (const float*)d_in[28];
    const float* Wc    = (const float*)d_in[29]; const float* bc   = (const float*)d_in[30];

    float *h1, *h2, *z1, *z3, *qkv, *obar, *h1mix, *ToM, *ToF, *part;
    __nv_bfloat16 *G1h, *G1l, *G3h, *G3l, *BtYh, *BtYl, *BtWh, *BtWl;
    __nv_bfloat16 *mixh, *mixl, *fush, *fusl;
    cudaGetSymbolAddress((void**)&h1,    g_h1);
    cudaGetSymbolAddress((void**)&h2,    g_h2);
    cudaGetSymbolAddress((void**)&z1,    g_z1);
    cudaGetSymbolAddress((void**)&z3,    g_z3);
    cudaGetSymbolAddress((void**)&qkv,   g_qkv);
    cudaGetSymbolAddress((void**)&obar,  g_obar);
    cudaGetSymbolAddress((void**)&h1mix, g_h1mix);
    cudaGetSymbolAddress((void**)&ToM,   g_ToM);
    cudaGetSymbolAddress((void**)&ToF,   g_ToF);
    cudaGetSymbolAddress((void**)&part,  g_part);
    cudaGetSymbolAddress((void**)&G1h,   g_G1h);
    cudaGetSymbolAddress((void**)&G1l,   g_G1l);
    cudaGetSymbolAddress((void**)&G3h,   g_G3h);
    cudaGetSymbolAddress((void**)&G3l,   g_G3l);
    cudaGetSymbolAddress((void**)&BtYh,  g_BtYh);
    cudaGetSymbolAddress((void**)&BtYl,  g_BtYl);
    cudaGetSymbolAddress((void**)&BtWh,  g_BtWh);
    cudaGetSymbolAddress((void**)&BtWl,  g_BtWl);
    cudaGetSymbolAddress((void**)&mixh,  g_mixh);
    cudaGetSymbolAddress((void**)&mixl,  g_mixl);
    cudaGetSymbolAddress((void**)&fush,  g_fush);
    cudaGetSymbolAddress((void**)&fusl,  g_fusl);

    float* out = (float*)d_out;
    float* h3  = out + (size_t)EE * 2;

    const int red_grid = (NN * HH / 4 + 255) / 256;
    const dim3 sg_grid(NN / BM, 1);

    // one-time conversions
    gsplit_kernel<<<(NN * NN / 4 + 255) / 256, 256>>>(G1, G1h, G1l, NN * NN);
    gsplit_kernel<<<(NN * NN / 4 + 255) / 256, 256>>>(G3, G3h, G3l, NN * NN);
    transpose_kernel<<<(HH * HH + 255) / 256, 256>>>(WoM, ToM, HH, HH);
    transpose_kernel<<<(HH * HH + 255) / 256, 256>>>(WoF, ToF, HH, HH);

    // h1 = relu(G1 @ (x W1 + b1))
    sgemm_bt_kernel<<<sg_grid, 256>>>(x, W1, BtYh, BtYl, NN, HH, HH, b1);
    tgemm(G1h, G1l, BtYh, BtYl, part, NN, NN, HH, nullptr, 4);
    reduce4_kernel<<<red_grid, 256>>>(part, h1, nullptr, 1, nullptr, nullptr, nullptr);

    // h2 = relu(G1 @ (h1 W2 + b2) + h1)
    sgemm_bt_kernel<<<sg_grid, 256>>>(h1, W2, BtYh, BtYl, NN, HH, HH, b2);
    tgemm(G1h, G1l, BtYh, BtYl, part, NN, NN, HH, nullptr, 4);
    reduce4_kernel<<<red_grid, 256>>>(part, h2, h1, 1, nullptr, nullptr, nullptr);

    // h3_c1 -> fus[0] (bf16 only)
    sgemm_bt_kernel<<<sg_grid, 256>>>(h2, W3, BtYh, BtYl, NN, HH, HH, b3);
    tgemm(G1h, G1l, BtYh, BtYl, part, NN, NN, HH, nullptr, 4);
    reduce4_kernel<<<red_grid, 256>>>(part, nullptr, h2, 1, nullptr, fush, fusl);

    // z1 = G1 @ (h1 W1h + b1h)
    sgemm_bt_kernel<<<sg_grid, 256>>>(h1, W1h, BtYh, BtYl, NN, HH, HH, b1h);
    tgemm(G1h, G1l, BtYh, BtYl, part, NN, NN, HH, nullptr, 4);
    reduce4_kernel<<<red_grid, 256>>>(part, z1, nullptr, 0, nullptr, nullptr, nullptr);

    // z3 = G3 @ (h1 W3h + b3h)
    sgemm_bt_kernel<<<sg_grid, 256>>>(h1, W3h, BtYh, BtYl, NN, HH, HH, b3h);
    tgemm(G3h, G3l, BtYh, BtYl, part, NN, NN, HH, nullptr, 4);
    reduce4_kernel<<<red_grid, 256>>>(part, z3, nullptr, 0, nullptr, nullptr, nullptr);

    // mixup (permuted-graph term == z[perm]); emits bf16 hi/lo stack
    mixcombine_kernel<<<(NN * HH / 2 + 255) / 256, 256>>>(z1, z3, perm, lam, mixh, mixl);

    // MHA mix (nh=2)
    convnt_kernel<<<(3 * HH * HH + 255) / 256, 256>>>(WqkvM, BtWh, BtWl, 3 * HH * HH);
    tgemm(mixh, mixl, BtWh, BtWl, qkv, 2 * NN, HH, 3 * HH, bqkvM, 1);
    attn_kernel<<<(NN * 2 + 255) / 256, 256>>>(qkv, obar, 2);
    sgemm_kernel<<<sg_grid, 256>>>(obar, ToM, h1mix, NN, HH, HH, boM);

    // h2_mix = relu(G1 @ (h1mix W2m + b2m) + h1mix)
    sgemm_bt_kernel<<<sg_grid, 256>>>(h1mix, W2m, BtYh, BtYl, NN, HH, HH, b2m);
    tgemm(G1h, G1l, BtYh, BtYl, part, NN, NN, HH, nullptr, 4);
    reduce4_kernel<<<red_grid, 256>>>(part, h2, h1mix, 1, nullptr, nullptr, nullptr);

    // h3_c2 = relu(G1 @ (h2mix W3m + b3m) + h2mix) * beta -> fus[1] (bf16 only)
    sgemm_bt_kernel<<<sg_grid, 256>>>(h2, W3m, BtYh, BtYl, NN, HH, HH, b3m);
    tgemm(G1h, G1l, BtYh, BtYl, part, NN, NN, HH, nullptr, 4);
    reduce4_kernel<<<red_grid, 256>>>(part, nullptr, h2, 1, beta,
                                      fush + (size_t)NN * HH, fusl + (size_t)NN * HH);

    // MHA fus (nh=4)
    convnt_kernel<<<(3 * HH * HH + 255) / 256, 256>>>(WqkvF, BtWh, BtWl, 3 * HH * HH);
    tgemm(fush, fusl, BtWh, BtWl, qkv, 2 * NN, HH, 3 * HH, bqkvF, 1);
    attn_kernel<<<(NN * 4 + 255) / 256, 256>>>(qkv, obar, 4);
    sgemm_kernel<<<sg_grid, 256>>>(obar, ToF, h3, NN, HH, HH, boF);

    // edge predictions
    edge_kernel<<<EE / 8, 256>>>(h3, ei, Wc, bc, out);
}